// round 15
// baseline (speedup 1.0000x reference)
#include <cuda_runtime.h>
#include <cuda_bf16.h>
#include <mma.h>
#include <cstdint>

using namespace nvcuda;

// Tropical (max-plus) Gram matrix via log-sum-exp GEMM on HMMA (wmma bf16).
// H[i,j] = m_i + m_j + log( sum_k e^{L(|W_ik|-m_i)} e^{L(|W_jk|-m_j)} ) / L
// R15 = R14 with the prep smem buffer correctly sized (10000 floats, was
// 2512 -> out-of-bounds smem writes -> illegal memory access).

constexpr int N_DIM = 2048;
constexpr int K_DIM = 10000;
constexpr int KHALF_PAD = 5056;                // 79 * 64
constexpr int K_PAD = 2 * KHALF_PAD;           // 10112
constexpr float LMB = 2600.0f;
constexpr int NTILES = 16;
constexpr int NPAIRS = 136;
constexpr int KTS  = 64;                       // k per pipeline stage
constexpr int NSTG = KHALF_PAD / KTS;          // 79
constexpr int ESTR = 72;                       // smem row stride (bf16) = 144B
constexpr int STAGE_BYTES = 128 * ESTR * 2;    // 18432 per operand
constexpr int NBUF = 3;
constexpr int PIPE_BYTES = NBUF * 2 * STAGE_BYTES;   // 110592 (> scratch 67584)
constexpr int NTHR = 256;
constexpr int LDC = 132;                       // epilogue scratch stride (floats)

__device__ __nv_bfloat16 g_E[(size_t)N_DIM * K_PAD];
__device__ float g_m[N_DIM];
__device__ float g_P[(size_t)N_DIM * N_DIM];   // cross-exported partial sums
__device__ int   g_flag[NPAIRS * 2];

__device__ __forceinline__ uint32_t smem_u32(const void* p) {
    uint32_t a;
    asm("{ .reg .u64 t; cvta.to.shared.u64 t, %1; cvt.u32.u64 %0, t; }" : "=r"(a) : "l"(p));
    return a;
}
__device__ __forceinline__ void cp16(uint32_t dst, const void* src) {
    asm volatile("cp.async.cg.shared.global [%0], [%1], 16;" :: "r"(dst), "l"(src) : "memory");
}
__device__ __forceinline__ void cp_commit() {
    asm volatile("cp.async.commit_group;" ::: "memory");
}
template <int N>
__device__ __forceinline__ void cp_wait() {
    asm volatile("cp.async.wait_group %0;" :: "n"(N) : "memory");
}

// ------- kernel 1: smem-staged rowmax + E = bf16(exp(L*(|W|-m))) -------
__global__ void prep_kernel(const float* __restrict__ W) {
    __shared__ __align__(16) float absrow[10016];  // 10000 used (floats) + pad
    __shared__ float red[8];
    __shared__ float mbc;

    const int i = blockIdx.x;
    const int t = threadIdx.x;
    if (t == 0 && i < NPAIRS * 2) g_flag[i] = 0;   // zero split-K flags

    const float4* row4 = (const float4*)(W + (size_t)i * K_DIM);
    float m = 0.0f;
#pragma unroll
    for (int q = 0; q < 10; ++q) {
        int c = t + 256 * q;
        if (c < K_DIM / 4) {
            float4 v = row4[c];
            v.x = fabsf(v.x); v.y = fabsf(v.y); v.z = fabsf(v.z); v.w = fabsf(v.w);
            *(float4*)&absrow[c * 4] = v;
            m = fmaxf(m, fmaxf(fmaxf(v.x, v.y), fmaxf(v.z, v.w)));
        }
    }
#pragma unroll
    for (int o = 16; o; o >>= 1) m = fmaxf(m, __shfl_xor_sync(~0u, m, o));
    if ((t & 31) == 0) red[t >> 5] = m;
    __syncthreads();
    if (t < 8) {
        float w = red[t];
#pragma unroll
        for (int o = 4; o; o >>= 1) w = fmaxf(w, __shfl_xor_sync(0xffu, w, o));
        if (t == 0) { mbc = w; g_m[i] = w; }
    }
    __syncthreads();
    const float mv = mbc;

    __nv_bfloat16* erow = g_E + (size_t)i * K_PAD;
#pragma unroll
    for (int q = 0; q < 10; ++q) {
        int c = t + 256 * q;
        if (c < K_DIM / 4) {
            float4 v = *(const float4*)&absrow[c * 4];
            __nv_bfloat16 o[4];
            o[0] = __float2bfloat16(__expf((v.x - mv) * LMB));
            o[1] = __float2bfloat16(__expf((v.y - mv) * LMB));
            o[2] = __float2bfloat16(__expf((v.z - mv) * LMB));
            o[3] = __float2bfloat16(__expf((v.w - mv) * LMB));
            *(uint2*)(erow + c * 4) = *(const uint2*)o;
        }
    }
    if (t < 56) *(uint32_t*)(erow + K_DIM + 2 * t) = 0u;   // zero pad
}

// ------- kernel 2: wmma bf16 GEMM + symmetric split-K epilogue -------
__global__ void __launch_bounds__(NTHR, 2)
lse_gemm_kernel(float* __restrict__ H)
{
    extern __shared__ char smem[];
    const uint32_t sb = smem_u32(smem);
    const int tid = (int)threadIdx.x;
    const int wid = tid >> 5;

    int rem = (int)blockIdx.x;
    int ti = 0;
    while (rem >= NTILES - ti) { rem -= NTILES - ti; ++ti; }
    const int tj = ti + rem;
    const int gi = ti * 128, gj = tj * 128;
    const int ky = (int)blockIdx.y;
    const int bx = (int)blockIdx.x;
    const size_t kbase = (size_t)ky * KHALF_PAD;

    __shared__ float mi_s[128], mj_s[128];
    // hoist: hide g_m global latency under the mainloop
    if (tid < 128) { mi_s[tid] = g_m[gi + tid]; mj_s[tid] = g_m[gj + tid]; }

    // warp grid 4(m) x 2(n): each warp 32(m) x 64(n)
    const int m0 = (wid & 3) * 32;
    const int n0 = (wid >> 2) * 64;

    wmma::fragment<wmma::accumulator, 16, 16, 16, float> acc[2][4];
#pragma unroll
    for (int a = 0; a < 2; ++a)
#pragma unroll
        for (int b = 0; b < 4; ++b) wmma::fill_fragment(acc[a][b], 0.0f);

    auto prefetch = [&](int s) {
        const int buf = s % NBUF;
        const uint32_t abase = sb + (uint32_t)buf * 2 * STAGE_BYTES;
        const uint32_t bbase = abase + STAGE_BYTES;
#pragma unroll
        for (int q = 0; q < 8; ++q) {
            int c = tid + NTHR * q;           // 0..2047
            int isB = c >> 10;
            int cc = c & 1023;
            int row = cc >> 3, sub = cc & 7;  // 8 x 16B = 128B per row
            uint32_t dst = (isB ? bbase : abase) + (uint32_t)(row * (ESTR * 2) + sub * 16);
            const __nv_bfloat16* src =
                g_E + (size_t)((isB ? gj : gi) + row) * K_PAD + kbase + (size_t)s * KTS + sub * 8;
            cp16(dst, src);
        }
        cp_commit();
    };

    prefetch(0); prefetch(1);

    typedef wmma::fragment<wmma::matrix_a, 16, 16, 16, __nv_bfloat16, wmma::row_major> FragA;
    typedef wmma::fragment<wmma::matrix_b, 16, 16, 16, __nv_bfloat16, wmma::col_major> FragB;

#pragma unroll 1
    for (int s = 0; s < NSTG; ++s) {
        if (s >= NSTG - 1) cp_wait<0>();
        else               cp_wait<1>();
        __syncthreads();
        if (s + 2 < NSTG) prefetch(s + 2);

        const int buf = s % NBUF;
        const __nv_bfloat16* A = (const __nv_bfloat16*)(smem + buf * 2 * STAGE_BYTES);
        const __nv_bfloat16* B = (const __nv_bfloat16*)(smem + buf * 2 * STAGE_BYTES + STAGE_BYTES);

        FragA af[2][2];
        FragB bfr[2][4];
#pragma unroll
        for (int a = 0; a < 2; ++a)
            wmma::load_matrix_sync(af[0][a], A + (m0 + a * 16) * ESTR, ESTR);
#pragma unroll
        for (int b = 0; b < 4; ++b)
            wmma::load_matrix_sync(bfr[0][b], B + (n0 + b * 16) * ESTR, ESTR);

#pragma unroll
        for (int kki = 0; kki < 4; ++kki) {
            const int cb = kki & 1, nb = cb ^ 1;
            if (kki < 3) {
                const int kk = (kki + 1) * 16;
#pragma unroll
                for (int a = 0; a < 2; ++a)
                    wmma::load_matrix_sync(af[nb][a], A + (m0 + a * 16) * ESTR + kk, ESTR);
#pragma unroll
                for (int b = 0; b < 4; ++b)
                    wmma::load_matrix_sync(bfr[nb][b], B + (n0 + b * 16) * ESTR + kk, ESTR);
            }
#pragma unroll
            for (int a = 0; a < 2; ++a)
#pragma unroll
                for (int b = 0; b < 4; ++b)
                    wmma::mma_sync(acc[a][b], af[cb][a], bfr[cb][b], acc[a][b]);
        }
    }
    __syncthreads();   // mainloop done; safe to reuse pipeline smem as scratch

    // ---- symmetric split epilogue ----
    float* scratch = (float*)smem;
    const int own0   = 64 * ky;        // rows this CTA finalizes
    const int other0 = 64 - own0;      // rows this CTA exports

    // 1) all warps dump acc into full-tile smem scratch
#pragma unroll
    for (int a = 0; a < 2; ++a)
#pragma unroll
        for (int b = 0; b < 4; ++b)
            wmma::store_matrix_sync(scratch + (size_t)(m0 + a * 16) * LDC + (n0 + b * 16),
                                    acc[a][b], LDC, wmma::mem_row_major);
    __syncthreads();

    // 2) export other half's rows to g_P, coalesced float4
#pragma unroll
    for (int q = 0; q < 8; ++q) {
        int idx = tid + 256 * q;
        int rr = idx >> 5, c4 = (idx & 31) * 4;
        float4 v = *(float4*)&scratch[(other0 + rr) * LDC + c4];
        *(float4*)&g_P[(size_t)(gi + other0 + rr) * N_DIM + gj + c4] = v;
    }
    __threadfence();
    __syncthreads();
    if (tid == 0) {
        atomicExch(&g_flag[2 * bx + ky], 1);
        while (atomicAdd(&g_flag[2 * bx + (1 - ky)], 0) == 0) __nanosleep(64);
        __threadfence();
    }
    __syncthreads();

    // 3) combine own rows: log(own_scratch + partner_gP), write H, keep for mirror
    const float invL = 1.0f / LMB;
#pragma unroll
    for (int q = 0; q < 8; ++q) {
        int idx = tid + 256 * q;
        int rr = idx >> 5, c4 = (idx & 31) * 4;
        int r = own0 + rr;
        float* srow = &scratch[r * LDC + c4];
        float4 p0 = *(float4*)srow;
        float4 p1 = *(const float4*)&g_P[(size_t)(gi + r) * N_DIM + gj + c4];
        float base = mi_s[r];
        float4 v;
        v.x = base + mj_s[c4 + 0] + __logf(p0.x + p1.x) * invL;
        v.y = base + mj_s[c4 + 1] + __logf(p0.y + p1.y) * invL;
        v.z = base + mj_s[c4 + 2] + __logf(p0.z + p1.z) * invL;
        v.w = base + mj_s[c4 + 3] + __logf(p0.w + p1.w) * invL;
        *(float4*)&H[(size_t)(gi + r) * N_DIM + gj + c4] = v;
        srow[0] = v.x; srow[1] = v.y; srow[2] = v.z; srow[3] = v.w;
    }

    if (ti == tj) return;   // diagonal: both halves wrote full width; no mirror

    __syncthreads();
    // 4) mirror own 64-column slice: H[gj+c][gi+own0+rr] = v[own0+rr][c]
#pragma unroll
    for (int q = 0; q < 8; ++q) {
        int idx = tid + 256 * q;
        int c  = idx >> 4;                 // 0..127
        int r4 = (idx & 15) * 4;           // 0..60
        float4 v;
        v.x = scratch[(own0 + r4 + 0) * LDC + c];
        v.y = scratch[(own0 + r4 + 1) * LDC + c];
        v.z = scratch[(own0 + r4 + 2) * LDC + c];
        v.w = scratch[(own0 + r4 + 3) * LDC + c];
        *(float4*)&H[(size_t)(gj + c) * N_DIM + gi + own0 + r4] = v;
    }
}

// ---------------- launcher ----------------
extern "C" void kernel_launch(void* const* d_in, const int* in_sizes, int n_in,
                              void* d_out, int out_size) {
    const float* W = (const float*)d_in[0];
    float* H = (float*)d_out;

    cudaFuncSetAttribute(lse_gemm_kernel, cudaFuncAttributeMaxDynamicSharedMemorySize, PIPE_BYTES);

    prep_kernel<<<N_DIM, 256>>>(W);
    dim3 gg(NPAIRS, 2);
    lse_gemm_kernel<<<gg, NTHR, PIPE_BYTES>>>(H);
}

// round 16
// speedup vs baseline: 1.0302x; 1.0302x over previous
#include <cuda_runtime.h>
#include <cuda_bf16.h>
#include <mma.h>
#include <cstdint>

using namespace nvcuda;

// Tropical (max-plus) Gram matrix via log-sum-exp GEMM on HMMA (wmma bf16).
// H[i,j] = m_i + m_j + log( sum_k e^{L(|W_ik|-m_i)} e^{L(|W_jk|-m_j)} ) / L
// R16 vs R13: the two K-half CTAs of each tile form a cluster (1,2,1) and
// exchange partial tiles via DSMEM (ld.shared::cluster) instead of a global
// g_P round-trip + flag protocol. Prep reverted to R13 register version
// (R15's smem staging regressed). Combine order p0+p1 unchanged -> rel_err
// bit-identical.

constexpr int N_DIM = 2048;
constexpr int K_DIM = 10000;
constexpr int KHALF_PAD = 5056;                // 79 * 64
constexpr int K_PAD = 2 * KHALF_PAD;           // 10112
constexpr float LMB = 2600.0f;
constexpr int NTILES = 16;
constexpr int NPAIRS = 136;
constexpr int KTS  = 64;                       // k per pipeline stage
constexpr int NSTG = KHALF_PAD / KTS;          // 79
constexpr int ESTR = 72;                       // smem row stride (bf16) = 144B
constexpr int STAGE_BYTES = 128 * ESTR * 2;    // 18432 per operand
constexpr int NBUF = 3;
constexpr int PIPE_BYTES = NBUF * 2 * STAGE_BYTES;   // 110592 (> scratch 67584)
constexpr int NTHR = 256;
constexpr int LDC = 132;                       // epilogue scratch stride (floats)

__device__ __nv_bfloat16 g_E[(size_t)N_DIM * K_PAD];
__device__ float g_m[N_DIM];

__device__ __forceinline__ uint32_t smem_u32(const void* p) {
    uint32_t a;
    asm("{ .reg .u64 t; cvta.to.shared.u64 t, %1; cvt.u32.u64 %0, t; }" : "=r"(a) : "l"(p));
    return a;
}
__device__ __forceinline__ void cp16(uint32_t dst, const void* src) {
    asm volatile("cp.async.cg.shared.global [%0], [%1], 16;" :: "r"(dst), "l"(src) : "memory");
}
__device__ __forceinline__ void cp_commit() {
    asm volatile("cp.async.commit_group;" ::: "memory");
}
template <int N>
__device__ __forceinline__ void cp_wait() {
    asm volatile("cp.async.wait_group %0;" :: "n"(N) : "memory");
}
__device__ __forceinline__ uint32_t mapa_remote(uint32_t addr, uint32_t rank) {
    uint32_t r;
    asm("mapa.shared::cluster.u32 %0, %1, %2;" : "=r"(r) : "r"(addr), "r"(rank));
    return r;
}
__device__ __forceinline__ float4 ld_dsmem4(uint32_t addr) {
    float4 v;
    asm volatile("ld.shared::cluster.v4.f32 {%0,%1,%2,%3}, [%4];"
                 : "=f"(v.x), "=f"(v.y), "=f"(v.z), "=f"(v.w) : "r"(addr));
    return v;
}
__device__ __forceinline__ void cluster_sync() {
    asm volatile("barrier.cluster.arrive.aligned;" ::: "memory");
    asm volatile("barrier.cluster.wait.aligned;" ::: "memory");
}

// ------- kernel 1: reg-resident rowmax + E = bf16(exp(L*(|W|-m))) -------
__global__ void prep_kernel(const float* __restrict__ W) {
    const int i = blockIdx.x;
    const int t = threadIdx.x;

    const float4* row4 = (const float4*)(W + (size_t)i * K_DIM);
    float4 v[10];
    float m = 0.0f;
#pragma unroll
    for (int q = 0; q < 10; ++q) {
        int c = t + 256 * q;
        if (c < K_DIM / 4) {
            v[q] = row4[c];
            m = fmaxf(m, fmaxf(fmaxf(fabsf(v[q].x), fabsf(v[q].y)),
                               fmaxf(fabsf(v[q].z), fabsf(v[q].w))));
        }
    }
#pragma unroll
    for (int o = 16; o; o >>= 1) m = fmaxf(m, __shfl_xor_sync(~0u, m, o));
    __shared__ float red[8];
    __shared__ float mbc;
    if ((t & 31) == 0) red[t >> 5] = m;
    __syncthreads();
    if (t < 8) {
        float w = red[t];
#pragma unroll
        for (int o = 4; o; o >>= 1) w = fmaxf(w, __shfl_xor_sync(0xffu, w, o));
        if (t == 0) { mbc = w; g_m[i] = w; }
    }
    __syncthreads();
    const float mv = mbc;

    __nv_bfloat16* erow = g_E + (size_t)i * K_PAD;
#pragma unroll
    for (int q = 0; q < 10; ++q) {
        int c = t + 256 * q;
        if (c < K_DIM / 4) {
            __nv_bfloat16 o[4];
            o[0] = __float2bfloat16(__expf((fabsf(v[q].x) - mv) * LMB));
            o[1] = __float2bfloat16(__expf((fabsf(v[q].y) - mv) * LMB));
            o[2] = __float2bfloat16(__expf((fabsf(v[q].z) - mv) * LMB));
            o[3] = __float2bfloat16(__expf((fabsf(v[q].w) - mv) * LMB));
            *(uint2*)(erow + c * 4) = *(const uint2*)o;
        }
    }
    if (t < 56) *(uint32_t*)(erow + K_DIM + 2 * t) = 0u;   // zero pad
}

// ------- kernel 2: wmma bf16 GEMM + DSMEM split-K epilogue -------
__global__ void __launch_bounds__(NTHR, 2) __cluster_dims__(1, 2, 1)
lse_gemm_kernel(float* __restrict__ H)
{
    extern __shared__ char smem[];
    const uint32_t sb = smem_u32(smem);
    const int tid = (int)threadIdx.x;
    const int wid = tid >> 5;

    int rem = (int)blockIdx.x;
    int ti = 0;
    while (rem >= NTILES - ti) { rem -= NTILES - ti; ++ti; }
    const int tj = ti + rem;
    const int gi = ti * 128, gj = tj * 128;
    const int ky = (int)blockIdx.y;            // == cluster ctarank
    const size_t kbase = (size_t)ky * KHALF_PAD;

    __shared__ float mi_s[128], mj_s[128];
    if (tid < 128) { mi_s[tid] = g_m[gi + tid]; mj_s[tid] = g_m[gj + tid]; }

    // warp grid 4(m) x 2(n): each warp 32(m) x 64(n)
    const int m0 = (wid & 3) * 32;
    const int n0 = (wid >> 2) * 64;

    wmma::fragment<wmma::accumulator, 16, 16, 16, float> acc[2][4];
#pragma unroll
    for (int a = 0; a < 2; ++a)
#pragma unroll
        for (int b = 0; b < 4; ++b) wmma::fill_fragment(acc[a][b], 0.0f);

    auto prefetch = [&](int s) {
        const int buf = s % NBUF;
        const uint32_t abase = sb + (uint32_t)buf * 2 * STAGE_BYTES;
        const uint32_t bbase = abase + STAGE_BYTES;
#pragma unroll
        for (int q = 0; q < 8; ++q) {
            int c = tid + NTHR * q;           // 0..2047
            int isB = c >> 10;
            int cc = c & 1023;
            int row = cc >> 3, sub = cc & 7;  // 8 x 16B = 128B per row
            uint32_t dst = (isB ? bbase : abase) + (uint32_t)(row * (ESTR * 2) + sub * 16);
            const __nv_bfloat16* src =
                g_E + (size_t)((isB ? gj : gi) + row) * K_PAD + kbase + (size_t)s * KTS + sub * 8;
            cp16(dst, src);
        }
        cp_commit();
    };

    prefetch(0); prefetch(1);

    typedef wmma::fragment<wmma::matrix_a, 16, 16, 16, __nv_bfloat16, wmma::row_major> FragA;
    typedef wmma::fragment<wmma::matrix_b, 16, 16, 16, __nv_bfloat16, wmma::col_major> FragB;

#pragma unroll 1
    for (int s = 0; s < NSTG; ++s) {
        if (s >= NSTG - 1) cp_wait<0>();
        else               cp_wait<1>();
        __syncthreads();
        if (s + 2 < NSTG) prefetch(s + 2);

        const int buf = s % NBUF;
        const __nv_bfloat16* A = (const __nv_bfloat16*)(smem + buf * 2 * STAGE_BYTES);
        const __nv_bfloat16* B = (const __nv_bfloat16*)(smem + buf * 2 * STAGE_BYTES + STAGE_BYTES);

        FragA af[2][2];
        FragB bfr[2][4];
#pragma unroll
        for (int a = 0; a < 2; ++a)
            wmma::load_matrix_sync(af[0][a], A + (m0 + a * 16) * ESTR, ESTR);
#pragma unroll
        for (int b = 0; b < 4; ++b)
            wmma::load_matrix_sync(bfr[0][b], B + (n0 + b * 16) * ESTR, ESTR);

#pragma unroll
        for (int kki = 0; kki < 4; ++kki) {
            const int cb = kki & 1, nb = cb ^ 1;
            if (kki < 3) {
                const int kk = (kki + 1) * 16;
#pragma unroll
                for (int a = 0; a < 2; ++a)
                    wmma::load_matrix_sync(af[nb][a], A + (m0 + a * 16) * ESTR + kk, ESTR);
#pragma unroll
                for (int b = 0; b < 4; ++b)
                    wmma::load_matrix_sync(bfr[nb][b], B + (n0 + b * 16) * ESTR + kk, ESTR);
            }
#pragma unroll
            for (int a = 0; a < 2; ++a)
#pragma unroll
                for (int b = 0; b < 4; ++b)
                    wmma::mma_sync(acc[a][b], af[cb][a], bfr[cb][b], acc[a][b]);
        }
    }
    __syncthreads();   // mainloop done; safe to reuse pipeline smem as scratch

    // ---- DSMEM split-K epilogue ----
    float* scratch = (float*)smem;
    const int own0 = 64 * ky;          // rows this CTA finalizes

    // 1) dump acc into full-tile smem scratch
#pragma unroll
    for (int a = 0; a < 2; ++a)
#pragma unroll
        for (int b = 0; b < 4; ++b)
            wmma::store_matrix_sync(scratch + (size_t)(m0 + a * 16) * LDC + (n0 + b * 16),
                                    acc[a][b], LDC, wmma::mem_row_major);

    // 2) cluster sync: both scratches complete & visible (release/acquire)
    cluster_sync();

    // 3) combine own rows: log(own + remote_partner), write H, store v back
    //    (own writes rows [own0,own0+64) — disjoint from partner's reads)
    const uint32_t rbase = mapa_remote(sb, (uint32_t)(1 - ky));
    const float invL = 1.0f / LMB;
#pragma unroll
    for (int q = 0; q < 8; ++q) {
        int idx = tid + 256 * q;
        int rr = idx >> 5, c4 = (idx & 31) * 4;
        int r = own0 + rr;
        float* srow = &scratch[r * LDC + c4];
        float4 p0 = *(float4*)srow;
        float4 p1 = ld_dsmem4(rbase + (uint32_t)((r * LDC + c4) * 4));
        float base = mi_s[r];
        float4 v;
        v.x = base + mj_s[c4 + 0] + __logf(p0.x + p1.x) * invL;
        v.y = base + mj_s[c4 + 1] + __logf(p0.y + p1.y) * invL;
        v.z = base + mj_s[c4 + 2] + __logf(p0.z + p1.z) * invL;
        v.w = base + mj_s[c4 + 3] + __logf(p0.w + p1.w) * invL;
        *(float4*)&H[(size_t)(gi + r) * N_DIM + gj + c4] = v;
        srow[0] = v.x; srow[1] = v.y; srow[2] = v.z; srow[3] = v.w;
    }

    // 4) cluster sync: all remote reads done before either CTA may exit;
    //    also orders own-scratch v writes before the mirror reads below
    cluster_sync();

    if (ti == tj) return;   // diagonal: both halves wrote full width; no mirror

    // 5) mirror own 64-column slice: H[gj+c][gi+own0+rr] = v[own0+rr][c]
#pragma unroll
    for (int q = 0; q < 8; ++q) {
        int idx = tid + 256 * q;
        int c  = idx >> 4;                 // 0..127
        int r4 = (idx & 15) * 4;           // 0..60
        float4 v;
        v.x = scratch[(own0 + r4 + 0) * LDC + c];
        v.y = scratch[(own0 + r4 + 1) * LDC + c];
        v.z = scratch[(own0 + r4 + 2) * LDC + c];
        v.w = scratch[(own0 + r4 + 3) * LDC + c];
        *(float4*)&H[(size_t)(gj + c) * N_DIM + gi + own0 + r4] = v;
    }
}

// ---------------- launcher ----------------
extern "C" void kernel_launch(void* const* d_in, const int* in_sizes, int n_in,
                              void* d_out, int out_size) {
    const float* W = (const float*)d_in[0];
    float* H = (float*)d_out;

    cudaFuncSetAttribute(lse_gemm_kernel, cudaFuncAttributeMaxDynamicSharedMemorySize, PIPE_BYTES);

    prep_kernel<<<N_DIM, 256>>>(W);
    dim3 gg(NPAIRS, 2);
    lse_gemm_kernel<<<gg, NTHR, PIPE_BYTES>>>(H);
}